// round 16
// baseline (speedup 1.0000x reference)
#include <cuda_runtime.h>

#define NFFT 640
#define HOP  320
#define NF   321            // freq bins
#define NT   301            // time frames
#define TLEN 96000
#define NCHF 17             // 16 x-channels + ref(b=0)
#define NFRF (NCHF*NT)      // 5117 forward frames
#define REFM0 (16*NT)       // 4816: start of ref-channel frames
#define MINV (7*NT)         // 2107 inverse frames
#define LPAD 96640
#define FT   (NF*NT)        // 96621
#define OFF_FEATS 768000

#define TWO_PI 6.283185307179586f

// table segment offsets inside k_tab's index space (float2 units)
#define TAB_CT4  0                       // 3840 (32*5*24) fwd stage1 radix-4 (20 r's, 24 slots)
#define TAB_T4   3840                    // 144  (8*18)    fwd stage2 radix-4 (17 q's, 18 slots)
#define TAB_TA   3984                    // 10880 (20*17*32)
#define TAB_TB   14864                   // 400   (transposed [n2][r])
#define TAB_WIN  15264                   // 640
#define TAB_INVW 15904                   // LPAD
#define TAB_END  (TAB_INVW + LPAD)

// ---------------- scratch (device globals; no allocation allowed) -------------
__device__ float  g_win[NFFT];
__device__ float  g_invw[LPAD];
__device__ float4 g_ct4[32*5*12];      // stage1: [n1][j<5][12 float4 = 24 slots], residue-grouped r
__device__ float4 g_T4[72];            // stage2: [j<8][9 float4 = 18 slots], residue-grouped q
__device__ float2 g_TA[20*17*32];      // inv stageA: [r][q][n1] = ck*(cos,+sin)(2pi k n1/640), k=20q+r (0 if k>320)
__device__ float2 g_TBt[20*20];        // inv stageB TRANSPOSED: [n2][r] = (cos,+sin)(2pi r n2/20)
__device__ float  g_framesT[NFFT*NFRF];// transposed windowed frames [n][m]
__device__ float2 g_Z[640*NFRF];       // fwd stage1 output, [(r*32+n1)][m]
__device__ float2 g_S[NF*NFRF];        // STFT, freq-major [f][m], m = ch*NT + t
__device__ float2 g_rp[323*309];       // padded refS (b=0)
__device__ float2 g_estF[NF*MINV];     // est freq-major [k][R], R = m*NT + t
__device__ float2 g_A1[640*MINV];      // inv stageA output, [(r*32+n1)][R]
__device__ float  g_y[MINV*NFFT];      // inverse frames (pre-OLA, windowed)

__device__ __forceinline__ float hannf(int n) {
    return 0.5f - 0.5f*cosf(TWO_PI * (float)n / (float)NFFT);
}

// stage2 slot (0..17) -> q grouped by residue mod 4 (17 q's: 5/4/4/4); -1 = pad
__device__ __forceinline__ int slot2q(int slot) {
    if (slot < 5)  return 4*slot;            // q = 0,4,8,12,16
    if (slot == 5) return -1;                // pad
    if (slot < 10) return 4*(slot-6) + 1;    // q = 1,5,9,13
    if (slot < 14) return 4*(slot-10) + 2;   // q = 2,6,10,14
    return 4*(slot-14) + 3;                  // q = 3,7,11,15
}

// stage1 slot (0..23) -> r grouped by residue mod 4 (20 r's: 5/5/5/5); -1 = pad
__device__ __forceinline__ int slot2r(int slot) {
    int g = slot / 6, i = slot - 6*g;        // group g = residue, i in [0,6)
    return (i < 5) ? (4*i + g) : -1;
}

// ---------------- init: all twiddle tables + window + invw (one launch) -------
__global__ void k_tab() {
    int idx = blockIdx.x*blockDim.x + threadIdx.x;
    if (idx < TAB_T4) {
        // stage1 radix-4 combined twiddle: e^{-2pi i r (n1+32j)/640}, residue-grouped r
        int n1 = idx / 120;                  // 5*24 = 120 float2 per n1
        int rem = idx - n1*120;
        int j = rem / 24, slot = rem - j*24;
        int r = slot2r(slot);
        float2 v = make_float2(0.f, 0.f);
        if (r >= 0) {
            float s, c;
            sincosf(TWO_PI * (float)((r*(n1 + 32*j)) % NFFT) / (float)NFFT, &s, &c);
            v = make_float2(c, -s);
        }
        ((float2*)g_ct4)[idx] = v;
    } else if (idx < TAB_TA) {
        // stage2 radix-4 twiddle: e^{-2pi i q j/32}, j<8, residue-grouped q
        int e = idx - TAB_T4;
        int j = e / 18, slot = e - j*18;
        int q = slot2q(slot);
        float2 v = make_float2(0.f, 0.f);
        if (q >= 0) {
            float s, c;
            sincosf(TWO_PI * (float)((q*j) % 32) / 32.0f, &s, &c);
            v = make_float2(c, -s);
        }
        ((float2*)g_T4)[e] = v;
    } else if (idx < TAB_TB) {
        // inv stageA: ck * e^{+2pi i k n1/640}, k = 20q+r
        int e = idx - TAB_TA;
        int r = e / 544;
        int rem = e - r*544;
        int q = rem / 32, n1 = rem - q*32;
        int k = 20*q + r;
        float2 v = make_float2(0.f, 0.f);
        if (k <= 320) {
            float ck = (k == 0 || k == 320) ? 1.0f : 2.0f;
            float s, c;
            sincosf(TWO_PI * (float)((k*n1) % NFFT) / (float)NFFT, &s, &c);
            v = make_float2(ck*c, ck*s);
        }
        g_TA[e] = v;
    } else if (idx < TAB_WIN) {
        // inv stageB transposed: [n2][r] = e^{+2pi i r n2/20}
        int e = idx - TAB_TB;
        int n2 = e / 20, r = e - n2*20;
        float s, c;
        sincosf(TWO_PI * (float)((r*n2) % 20) / 20.0f, &s, &c);
        g_TBt[e] = make_float2(c, s);
    } else if (idx < TAB_INVW) {
        int n = idx - TAB_WIN;
        g_win[n] = hannf(n);
    } else if (idx < TAB_END) {
        // closed-form inverse window sum (periodic interior, short edges)
        int sp = idx - TAB_INVW;
        float wsum;
        if (sp < HOP) {
            float w = hannf(sp);
            wsum = w*w;
        } else if (sp < 96320) {
            int n1 = sp % HOP;
            float w0 = hannf(n1), w1 = hannf(n1 + HOP);
            wsum = w0*w0 + w1*w1;
        } else {
            float w = hannf(sp - 96000);
            wsum = w*w;
        }
        g_invw[sp] = (wsum > 1e-11f) ? (1.0f/wsum) : 1.0f;
    }
}

// ---------------- framing (windowed, transposed output [n][m]), m-ranged ------
__global__ void k_framesT(const float* __restrict__ x, const float* __restrict__ ref,
                          int m_base, int m_end) {
    __shared__ float s[32][33];
    int tx = threadIdx.x, ty = threadIdx.y;   // block (32,8)
    int m0 = m_base + blockIdx.x * 32;
    int n0 = blockIdx.y * 32;
    int n = n0 + tx;
    float w = g_win[n];
    #pragma unroll
    for (int r4 = 0; r4 < 4; r4++) {
        int mr = ty + r4*8;
        int m = m0 + mr;
        float v = 0.0f;
        if (m < m_end) {
            int ch = m / NT;
            int t  = m - ch*NT;
            const float* sig = (ch < 16) ? (x + ch*TLEN) : ref;
            int p = t*HOP + n - HOP;
            if (p >= 0 && p < TLEN) v = sig[p];
        }
        s[mr][tx] = v * w;
    }
    __syncthreads();
    int m = m0 + tx;
    if (m < m_end) {
        #pragma unroll
        for (int r4 = 0; r4 < 4; r4++) {
            int nr = ty + r4*8;
            g_framesT[(n0 + nr)*NFRF + m] = s[tx][nr];
        }
    }
}

// ---------------- fwd stage 1 (radix-4 over n2 = j + 5k), m-ranged ------------
__global__ void __launch_bounds__(256) k_stage1(int m_base, int m_end) {
    __shared__ float  As[20][256];
    __shared__ float4 cts4s[60];           // [j<5][12 float4 = 24 slots]
    int m0 = m_base + blockIdx.x * 256;
    int n1 = blockIdx.y;
    int lid = threadIdx.x;

    #pragma unroll
    for (int i = 0; i < 20; i++) {
        int e = i*256 + lid;
        int n2 = e >> 8, ml = e & 255;
        int m = m0 + ml;
        As[n2][ml] = (m < m_end) ? g_framesT[(n1 + 32*n2)*NFRF + m] : 0.0f;
    }
    if (lid < 60) cts4s[lid] = g_ct4[n1*60 + lid];
    __syncthreads();

    float2 acc[20];
    #pragma unroll
    for (int r = 0; r < 20; r++) acc[r] = make_float2(0.f, 0.f);

    #pragma unroll
    for (int j = 0; j < 5; j++) {
        float u0 = As[j     ][lid];
        float u1 = As[j + 5 ][lid];
        float u2 = As[j + 10][lid];
        float u3 = As[j + 15][lid];
        float s02 = u0 + u2, d02 = u0 - u2;
        float s13 = u1 + u3, d13 = u1 - u3;
        float A0 = s02 + s13, A2 = s02 - s13;
        int b4 = j*12;
        float4 t;
        // r ≡ 0 (real A0): r = 0,4 | 8,12 | 16
        t = cts4s[b4+0];
        acc[0].x  += A0*t.x; acc[0].y  += A0*t.y; acc[4].x  += A0*t.z; acc[4].y  += A0*t.w;
        t = cts4s[b4+1];
        acc[8].x  += A0*t.x; acc[8].y  += A0*t.y; acc[12].x += A0*t.z; acc[12].y += A0*t.w;
        t = cts4s[b4+2];
        acc[16].x += A0*t.x; acc[16].y += A0*t.y;
        // r ≡ 1: B = d02 - i d13
        t = cts4s[b4+3];
        acc[1].x  += d02*t.x + d13*t.y; acc[1].y  += d02*t.y - d13*t.x;
        acc[5].x  += d02*t.z + d13*t.w; acc[5].y  += d02*t.w - d13*t.z;
        t = cts4s[b4+4];
        acc[9].x  += d02*t.x + d13*t.y; acc[9].y  += d02*t.y - d13*t.x;
        acc[13].x += d02*t.z + d13*t.w; acc[13].y += d02*t.w - d13*t.z;
        t = cts4s[b4+5];
        acc[17].x += d02*t.x + d13*t.y; acc[17].y += d02*t.y - d13*t.x;
        // r ≡ 2 (real A2): r = 2,6 | 10,14 | 18
        t = cts4s[b4+6];
        acc[2].x  += A2*t.x; acc[2].y  += A2*t.y; acc[6].x  += A2*t.z; acc[6].y  += A2*t.w;
        t = cts4s[b4+7];
        acc[10].x += A2*t.x; acc[10].y += A2*t.y; acc[14].x += A2*t.z; acc[14].y += A2*t.w;
        t = cts4s[b4+8];
        acc[18].x += A2*t.x; acc[18].y += A2*t.y;
        // r ≡ 3: B = d02 + i d13
        t = cts4s[b4+9];
        acc[3].x  += d02*t.x - d13*t.y; acc[3].y  += d02*t.y + d13*t.x;
        acc[7].x  += d02*t.z - d13*t.w; acc[7].y  += d02*t.w + d13*t.z;
        t = cts4s[b4+10];
        acc[11].x += d02*t.x - d13*t.y; acc[11].y += d02*t.y + d13*t.x;
        acc[15].x += d02*t.z - d13*t.w; acc[15].y += d02*t.w + d13*t.z;
        t = cts4s[b4+11];
        acc[19].x += d02*t.x - d13*t.y; acc[19].y += d02*t.y + d13*t.x;
    }

    int m = m0 + lid;
    if (m < m_end) {
        #pragma unroll
        for (int r = 0; r < 20; r++)
            g_Z[(r*32 + n1)*NFRF + m] = acc[r];
    }
}

// complex MAC: a += z * (tx + i ty)
#define CMAC(a, z, tx, ty) do { \
    (a).x += (z).x*(tx) - (z).y*(ty); \
    (a).y += (z).x*(ty) + (z).y*(tx); } while (0)

// ---------------- fwd stage 2 (radix-4 over n1 = j + 8k), m-ranged ------------
__global__ void __launch_bounds__(128) k_stage2(int m_base, int m_end) {
    __shared__ float2 Zs[32][128];
    __shared__ float4 T4s[72];             // [j<8][9 float4 = 18 slots]
    int m0 = m_base + blockIdx.x * 128;
    int r  = blockIdx.y;
    int lid = threadIdx.x;

    int m = m0 + lid;
    #pragma unroll
    for (int i = 0; i < 32; i++)
        Zs[i][lid] = (m < m_end) ? g_Z[(r*32 + i)*NFRF + m] : make_float2(0.f, 0.f);
    if (lid < 72) T4s[lid] = g_T4[lid];
    __syncthreads();

    float2 acc[17];
    #pragma unroll
    for (int q = 0; q < 17; q++) acc[q] = make_float2(0.f, 0.f);

    #pragma unroll
    for (int j = 0; j < 8; j++) {
        float2 za = Zs[j     ][lid];
        float2 zb = Zs[j + 8 ][lid];
        float2 zc = Zs[j + 16][lid];
        float2 zd = Zs[j + 24][lid];
        float2 s02 = make_float2(za.x + zc.x, za.y + zc.y);
        float2 d02 = make_float2(za.x - zc.x, za.y - zc.y);
        float2 s13 = make_float2(zb.x + zd.x, zb.y + zd.y);
        float2 d13 = make_float2(zb.x - zd.x, zb.y - zd.y);
        float2 A0 = make_float2(s02.x + s13.x, s02.y + s13.y);
        float2 A2 = make_float2(s02.x - s13.x, s02.y - s13.y);
        float2 A1 = make_float2(d02.x + d13.y, d02.y - d13.x);   // d02 - i d13
        float2 A3 = make_float2(d02.x - d13.y, d02.y + d13.x);   // d02 + i d13
        int b4 = j*9;
        float4 t;
        t = T4s[b4+0];  CMAC(acc[0],  A0, t.x, t.y);  CMAC(acc[4],  A0, t.z, t.w);
        t = T4s[b4+1];  CMAC(acc[8],  A0, t.x, t.y);  CMAC(acc[12], A0, t.z, t.w);
        t = T4s[b4+2];  CMAC(acc[16], A0, t.x, t.y);
        t = T4s[b4+3];  CMAC(acc[1],  A1, t.x, t.y);  CMAC(acc[5],  A1, t.z, t.w);
        t = T4s[b4+4];  CMAC(acc[9],  A1, t.x, t.y);  CMAC(acc[13], A1, t.z, t.w);
        t = T4s[b4+5];  CMAC(acc[2],  A2, t.x, t.y);  CMAC(acc[6],  A2, t.z, t.w);
        t = T4s[b4+6];  CMAC(acc[10], A2, t.x, t.y);  CMAC(acc[14], A2, t.z, t.w);
        t = T4s[b4+7];  CMAC(acc[3],  A3, t.x, t.y);  CMAC(acc[7],  A3, t.z, t.w);
        t = T4s[b4+8];  CMAC(acc[11], A3, t.x, t.y);  CMAC(acc[15], A3, t.z, t.w);
    }

    if (m < m_end) {
        #pragma unroll
        for (int q = 0; q < 17; q++) {
            int f = r + 20*q;
            if (f < NF) g_S[f*NFRF + m] = acc[q];
        }
    }
}

// ---------------- covariance features ----------------
__global__ void k_cov(float* __restrict__ out) {
    int idx = blockIdx.x*blockDim.x + threadIdx.x;
    if (idx >= 2*FT) return;
    int t = idx % NT;
    int f = (idx / NT) % NF;
    int b = idx / FT;
    float2 S[8];
    #pragma unroll
    for (int c = 0; c < 8; c++)
        S[c] = g_S[f*NFRF + (b*8 + c)*NT + t];
    float* o = out + OFF_FEATS + (b*74)*FT + f*NT + t;
    int p = 0;
    #pragma unroll
    for (int i = 0; i < 8; i++) {
        #pragma unroll
        for (int j = i; j < 8; j++) {
            float re = S[i].x*S[j].x + S[i].y*S[j].y;   // S_i * conj(S_j)
            float im = S[i].y*S[j].x - S[i].x*S[j].y;
            o[(2*p    )*FT] = re;
            o[(2*p + 1)*FT] = im;
            p++;
        }
    }
    o[72*FT] = S[3].x;
    o[73*FT] = S[3].y;
}

// ---------------- padded refS (b=0) ----------------
__global__ void k_refpad() {
    int idx = blockIdx.x*blockDim.x + threadIdx.x;
    if (idx >= 323*309) return;
    int fp = idx / 309, tp = idx - fp*309;
    int f = fp - 1, t = tp - 4;
    float2 v = make_float2(0.f, 0.f);
    if (f >= 0 && f < NF && t >= 0 && t < NT)
        v = g_S[f*NFRF + 16*NT + t];
    g_rp[idx] = v;
}

// ---------------- deep filtering (b=0 only), freq-major output ----------------
__global__ void k_deepfilter(const float2* __restrict__ rtf) {
    int idx = blockIdx.x*blockDim.x + threadIdx.x;
    if (idx >= 7*FT) return;
    int t = idx % NT;
    int f = (idx / NT) % NF;
    int m = idx / FT;
    const float2* rbase = rtf + m*27*FT + f*NT + t;  // b=0: [m][27][F][T] float2
    float2 acc = make_float2(0.f, 0.f);
    #pragma unroll
    for (int ki = 0; ki < 3; ki++) {
        #pragma unroll
        for (int kj = 0; kj < 9; kj++) {
            float2 r = rbase[(ki*9 + kj)*FT];
            float2 p = g_rp[(f + ki)*309 + (t + kj)];
            acc.x += r.x*p.x - r.y*p.y;
            acc.y += r.x*p.y + r.y*p.x;
        }
    }
    g_estF[f*MINV + m*NT + t] = acc;   // [k][R], R = m*NT + t
}

// ---------------- inv stage A: A1[r][n1][R] = sum_q ck*E[20q+r][R]*e^{+2pi i k n1/640}
// block 256 = 2 groups of 128; group g computes n1 in [16g, 16g+16)
__global__ void __launch_bounds__(256) k_istageA() {
    __shared__ float2 Es[17][128];
    __shared__ float2 TAs[17*32];
    int m0 = blockIdx.x * 128;
    int r  = blockIdx.y;
    int tid = threadIdx.x;
    int lid = tid & 127;
    int grp = tid >> 7;
    const float4* TAs4 = (const float4*)TAs;

    for (int e = tid; e < 544; e += 256) TAs[e] = g_TA[r*544 + e];
    for (int e = tid; e < 17*128; e += 256) {
        int q = e >> 7, ml = e & 127;
        int k = 20*q + r;
        int Rm = m0 + ml;
        Es[q][ml] = (k < NF && Rm < MINV) ? g_estF[k*MINV + Rm] : make_float2(0.f, 0.f);
    }
    __syncthreads();

    float2 acc[16];
    #pragma unroll
    for (int j = 0; j < 16; j++) acc[j] = make_float2(0.f, 0.f);

    #pragma unroll
    for (int q = 0; q < 17; q++) {
        float2 a = Es[q][lid];
        #pragma unroll
        for (int j = 0; j < 8; j++) {
            float4 t = TAs4[q*16 + grp*8 + j];
            acc[2*j  ].x += a.x*t.x - a.y*t.y;
            acc[2*j  ].y += a.x*t.y + a.y*t.x;
            acc[2*j+1].x += a.x*t.z - a.y*t.w;
            acc[2*j+1].y += a.x*t.w + a.y*t.z;
        }
    }

    int R = m0 + lid;
    int n1b = grp*16;
    if (R < MINV) {
        #pragma unroll
        for (int j = 0; j < 16; j++)
            g_A1[(r*32 + n1b + j)*MINV + R] = acc[j];
    }
}

// ---------------- inv stage B: y[R][n] = win[n]/640 * Re(sum_r A1[r][n1][R]*e^{+2pi i r n2/20})
__global__ void __launch_bounds__(256) k_istageB() {
    __shared__ float2 A1s[20][8][33];    // [r][mloc][n1] (pad to 33 for conflict-free)
    __shared__ float2 TBs[400];          // transposed [n2][r]
    __shared__ float  wins[NFFT];
    int R0 = blockIdx.x * 8;
    int lid = threadIdx.x;
    const float4* TBs4 = (const float4*)TBs;

    #pragma unroll
    for (int e = lid; e < 400; e += 256) TBs[e] = g_TBt[e];
    #pragma unroll
    for (int e = lid; e < NFFT; e += 256) wins[e] = g_win[e] * (1.0f/640.0f);
    #pragma unroll
    for (int i = 0; i < 20; i++) {
        int e = i*256 + lid;
        int rn1 = e >> 3, mloc = e & 7;
        int r = rn1 >> 5, n1 = rn1 & 31;
        int R = R0 + mloc;
        A1s[r][mloc][n1] = (R < MINV) ? g_A1[rn1*MINV + R] : make_float2(0.f, 0.f);
    }
    __syncthreads();

    #pragma unroll
    for (int mloc = 0; mloc < 8; mloc++) {
        int R = R0 + mloc;
        if (R >= MINV) break;    // uniform across block
        #pragma unroll
        for (int nb = 0; nb < 3; nb++) {
            int n = nb*256 + lid;
            if (n < NFFT) {
                int n1 = n & 31, n2 = n >> 5;
                float acc = 0.0f;
                #pragma unroll
                for (int jr = 0; jr < 10; jr++) {       // r = 2jr, 2jr+1
                    float4 t = TBs4[n2*10 + jr];
                    float2 a0 = A1s[2*jr  ][mloc][n1];
                    float2 a1 = A1s[2*jr+1][mloc][n1];
                    acc += a0.x*t.x - a0.y*t.y;
                    acc += a1.x*t.z - a1.y*t.w;
                }
                g_y[R*NFFT + n] = acc * wins[n];
            }
        }
    }
}

// ---------------- overlap-add + interleave output ----------------
__global__ void k_ola(const float* __restrict__ ref, float* __restrict__ out) {
    int s = blockIdx.x*blockDim.x + threadIdx.x;
    if (s >= TLEN) return;
    int sp = s + HOP;                 // position in uncropped signal
    int t1 = sp / HOP;                // in [1, 300]
    int n1 = sp - t1*HOP;             // [0, 320)
    int t0 = t1 - 1;
    int nn0 = n1 + HOP;               // [320, 640)
    float iw = g_invw[sp];
    float* o = out + s*8;
    #pragma unroll
    for (int m = 0; m < 7; m++) {
        float v = (g_y[(m*NT + t0)*NFFT + nn0] + g_y[(m*NT + t1)*NFFT + n1]) * iw;
        o[m < 3 ? m : m + 1] = v;
    }
    o[3] = ref[s];
}

// ---------------- launch: two independent chains on two streams ---------------
// Chain A (critical audio): fwd(ref only) -> refpad -> deepfilter -> inv -> ola
// Chain B (features):       fwd(16 x-channels) -> cov
extern "C" void kernel_launch(void* const* d_in, const int* in_sizes, int n_in,
                              void* d_out, int out_size) {
    const float*  x   = (const float*)d_in[0];
    const float2* rtf = (const float2*)d_in[1];  // [B][7][3][9][F][T][2]; b=0 slice
    const float*  ref = (const float*)d_in[2];   // [2][1][T]; b=0 slice
    float* out = (float*)d_out;

    cudaStream_t s2;
    cudaEvent_t evT, evC;
    cudaStreamCreateWithFlags(&s2, cudaStreamNonBlocking);
    cudaEventCreateWithFlags(&evT, cudaEventDisableTiming);
    cudaEventCreateWithFlags(&evC, cudaEventDisableTiming);

    // shared tables first, then fork
    k_tab<<<(TAB_END + 255)/256, 256>>>();
    cudaEventRecord(evT, 0);
    cudaStreamWaitEvent(s2, evT, 0);

    // ---- Chain B on side stream: feature forward + cov ----
    {
        dim3 g((REFM0 + 31)/32, NFFT/32);
        k_framesT<<<g, dim3(32, 8), 0, s2>>>(x, ref, 0, REFM0);
    }
    {
        dim3 g((REFM0 + 255)/256, 32);
        k_stage1<<<g, 256, 0, s2>>>(0, REFM0);
    }
    {
        dim3 g((REFM0 + 127)/128, 20);
        k_stage2<<<g, 128, 0, s2>>>(0, REFM0);
    }
    k_cov<<<(2*FT + 255)/256, 256, 0, s2>>>(out);
    cudaEventRecord(evC, s2);

    // ---- Chain A on main stream: ref forward + audio path ----
    {
        dim3 g((NT + 31)/32, NFFT/32);
        k_framesT<<<g, dim3(32, 8)>>>(x, ref, REFM0, NFRF);
    }
    {
        dim3 g((NT + 255)/256, 32);
        k_stage1<<<g, 256>>>(REFM0, NFRF);
    }
    {
        dim3 g((NT + 127)/128, 20);
        k_stage2<<<g, 128>>>(REFM0, NFRF);
    }
    k_refpad<<<(323*309 + 255)/256, 256>>>();
    k_deepfilter<<<(7*FT + 255)/256, 256>>>(rtf);
    {
        dim3 g((MINV + 127)/128, 20);
        k_istageA<<<g, 256>>>();
    }
    {
        dim3 g((MINV + 7)/8);
        k_istageB<<<g, 256>>>();
    }
    k_ola<<<(TLEN + 255)/256, 256>>>(ref, out);

    // join: main stream completes only after chain B
    cudaStreamWaitEvent(0, evC, 0);
}

// round 17
// speedup vs baseline: 1.0235x; 1.0235x over previous
#include <cuda_runtime.h>

#define NFFT 640
#define HOP  320
#define NF   321            // freq bins
#define NT   301            // time frames
#define TLEN 96000
#define NCHF 17             // 16 x-channels + ref(b=0)
#define NFRF (NCHF*NT)      // 5117 forward frames
#define MINV (7*NT)         // 2107 inverse frames
#define LPAD 96640
#define FT   (NF*NT)        // 96621
#define OFF_FEATS 768000

#define TWO_PI 6.283185307179586f

// table segment offsets inside k_tab's index space (float2 units)
#define TAB_CT4  0                       // 3840 (32*5*24) fwd stage1 radix-4 (20 r's, 24 slots)
#define TAB_T4   3840                    // 144  (8*18)    fwd stage2 radix-4 (17 q's, 18 slots)
#define TAB_TA   3984                    // 10880 (20*17*32)
#define TAB_TB   14864                   // 400   (transposed [n2][r])
#define TAB_WIN  15264                   // 640
#define TAB_INVW 15904                   // LPAD
#define TAB_END  (TAB_INVW + LPAD)

// ---------------- scratch (device globals; no allocation allowed) -------------
__device__ float  g_win[NFFT];
__device__ float  g_invw[LPAD];
__device__ float4 g_ct4[32*5*12];      // stage1: [n1][j<5][12 float4 = 24 slots], residue-grouped r
__device__ float4 g_T4[72];            // stage2: [j<8][9 float4 = 18 slots], residue-grouped q
__device__ float2 g_TA[20*17*32];      // inv stageA: [r][q][n1] = ck*(cos,+sin)(2pi k n1/640), k=20q+r (0 if k>320)
__device__ float2 g_TBt[20*20];        // inv stageB TRANSPOSED: [n2][r] = (cos,+sin)(2pi r n2/20)
__device__ float2 g_Z[640*NFRF];       // fwd stage1 output, [(r*32+n1)][m]
__device__ float2 g_S[NF*NFRF];        // STFT, freq-major [f][m], m = ch*NT + t
__device__ float2 g_rp[323*309];       // padded refS (b=0)
__device__ float2 g_estF[NF*MINV];     // est freq-major [k][R], R = m*NT + t
__device__ float2 g_A1[640*MINV];      // inv stageA output, [(r*32+n1)][R]
__device__ float  g_y[MINV*NFFT];      // inverse frames (pre-OLA, windowed)

__device__ __forceinline__ float hannf(int n) {
    return 0.5f - 0.5f*cosf(TWO_PI * (float)n / (float)NFFT);
}

// stage2 slot (0..17) -> q grouped by residue mod 4 (17 q's: 5/4/4/4); -1 = pad
__device__ __forceinline__ int slot2q(int slot) {
    if (slot < 5)  return 4*slot;            // q = 0,4,8,12,16
    if (slot == 5) return -1;                // pad
    if (slot < 10) return 4*(slot-6) + 1;    // q = 1,5,9,13
    if (slot < 14) return 4*(slot-10) + 2;   // q = 2,6,10,14
    return 4*(slot-14) + 3;                  // q = 3,7,11,15
}

// stage1 slot (0..23) -> r grouped by residue mod 4 (20 r's: 5/5/5/5); -1 = pad
__device__ __forceinline__ int slot2r(int slot) {
    int g = slot / 6, i = slot - 6*g;        // group g = residue, i in [0,6)
    return (i < 5) ? (4*i + g) : -1;
}

// ---------------- init: all twiddle tables + window + invw (one launch) -------
__global__ void k_tab() {
    int idx = blockIdx.x*blockDim.x + threadIdx.x;
    if (idx < TAB_T4) {
        // stage1 radix-4 combined twiddle: e^{-2pi i r (n1+32j)/640}, residue-grouped r
        int n1 = idx / 120;                  // 5*24 = 120 float2 per n1
        int rem = idx - n1*120;
        int j = rem / 24, slot = rem - j*24;
        int r = slot2r(slot);
        float2 v = make_float2(0.f, 0.f);
        if (r >= 0) {
            float s, c;
            sincosf(TWO_PI * (float)((r*(n1 + 32*j)) % NFFT) / (float)NFFT, &s, &c);
            v = make_float2(c, -s);
        }
        ((float2*)g_ct4)[idx] = v;
    } else if (idx < TAB_TA) {
        // stage2 radix-4 twiddle: e^{-2pi i q j/32}, j<8, residue-grouped q
        int e = idx - TAB_T4;
        int j = e / 18, slot = e - j*18;
        int q = slot2q(slot);
        float2 v = make_float2(0.f, 0.f);
        if (q >= 0) {
            float s, c;
            sincosf(TWO_PI * (float)((q*j) % 32) / 32.0f, &s, &c);
            v = make_float2(c, -s);
        }
        ((float2*)g_T4)[e] = v;
    } else if (idx < TAB_TB) {
        // inv stageA: ck * e^{+2pi i k n1/640}, k = 20q+r
        int e = idx - TAB_TA;
        int r = e / 544;
        int rem = e - r*544;
        int q = rem / 32, n1 = rem - q*32;
        int k = 20*q + r;
        float2 v = make_float2(0.f, 0.f);
        if (k <= 320) {
            float ck = (k == 0 || k == 320) ? 1.0f : 2.0f;
            float s, c;
            sincosf(TWO_PI * (float)((k*n1) % NFFT) / (float)NFFT, &s, &c);
            v = make_float2(ck*c, ck*s);
        }
        g_TA[e] = v;
    } else if (idx < TAB_WIN) {
        // inv stageB transposed: [n2][r] = e^{+2pi i r n2/20}
        int e = idx - TAB_TB;
        int n2 = e / 20, r = e - n2*20;
        float s, c;
        sincosf(TWO_PI * (float)((r*n2) % 20) / 20.0f, &s, &c);
        g_TBt[e] = make_float2(c, s);
    } else if (idx < TAB_INVW) {
        int n = idx - TAB_WIN;
        g_win[n] = hannf(n);
    } else if (idx < TAB_END) {
        // closed-form inverse window sum (periodic interior, short edges)
        int sp = idx - TAB_INVW;
        float wsum;
        if (sp < HOP) {
            float w = hannf(sp);
            wsum = w*w;
        } else if (sp < 96320) {
            int n1 = sp % HOP;
            float w0 = hannf(n1), w1 = hannf(n1 + HOP);
            wsum = w0*w0 + w1*w1;
        } else {
            float w = hannf(sp - 96000);
            wsum = w*w;
        }
        g_invw[sp] = (wsum > 1e-11f) ? (1.0f/wsum) : 1.0f;
    }
}

// ---------------- fused framing + fwd stage 1 ---------------------------------
// Block = (16 frames of one channel) x (all n1). Loads the contiguous 5440-sample
// x window into bank-padded smem, applies the Hann window at read time, and runs
// the radix-4 stage1 butterflies (verbatim from the validated k_stage1).
// smem: ct table 30720 B + win 2560 B + x_s 5460*4 B = 55120 B (dynamic)
#define FS1_SMEM (30720 + 2560 + 5460*4)
__global__ void __launch_bounds__(256) k_fs1(const float* __restrict__ x,
                                             const float* __restrict__ ref) {
    extern __shared__ char sm[];
    float4* ct_s  = (float4*)sm;                 // 1920 float4 (entire g_ct4)
    float*  win_s = (float*)(sm + 30720);        // 640
    float*  x_s   = win_s + 640;                 // 5460 (5440 + pads)
    int tile = blockIdx.x;    // t-tile: 0..18 (16 frames each)
    int ch   = blockIdx.y;    // 0..16
    int tid  = threadIdx.x;
    int m_local = tid & 15, n1g = tid >> 4;

    for (int e = tid; e < 1920; e += 256) ct_s[e] = g_ct4[e];
    for (int e = tid; e < 640; e += 256) win_s[e] = g_win[e];
    const float* sig = (ch < 16) ? (x + ch*TLEN) : ref;
    int p0 = tile*16*HOP - HOP;
    for (int i = tid; i < 5440; i += 256) {
        int p = p0 + i;
        x_s[i + i/320] = (p >= 0 && p < TLEN) ? sig[p] : 0.0f;  // bank-pad every 320
    }
    __syncthreads();

    int t = tile*16 + m_local;
    bool valid = (t < NT);
    int m = ch*NT + t;
    int bx = m_local*321;     // 320 + 1 pad per frame row

    #pragma unroll
    for (int it = 0; it < 2; it++) {
        int n1 = n1g + 16*it;
        float2 acc[20];
        #pragma unroll
        for (int r = 0; r < 20; r++) acc[r] = make_float2(0.f, 0.f);

        #pragma unroll
        for (int j = 0; j < 5; j++) {
            int nb = n1 + 32*j;
            // n2 = j, j+5 (n < 320: no pad), j+10, j+15 (n >= 320: +1 pad)
            float u0 = x_s[bx + nb      ] * win_s[nb      ];
            float u1 = x_s[bx + nb + 160] * win_s[nb + 160];
            float u2 = x_s[bx + nb + 321] * win_s[nb + 320];
            float u3 = x_s[bx + nb + 481] * win_s[nb + 480];
            float s02 = u0 + u2, d02 = u0 - u2;
            float s13 = u1 + u3, d13 = u1 - u3;
            float A0 = s02 + s13, A2 = s02 - s13;
            int b4 = n1*60 + j*12;
            float4 tt;
            // r ≡ 0 (real A0): r = 0,4 | 8,12 | 16
            tt = ct_s[b4+0];
            acc[0].x  += A0*tt.x; acc[0].y  += A0*tt.y; acc[4].x  += A0*tt.z; acc[4].y  += A0*tt.w;
            tt = ct_s[b4+1];
            acc[8].x  += A0*tt.x; acc[8].y  += A0*tt.y; acc[12].x += A0*tt.z; acc[12].y += A0*tt.w;
            tt = ct_s[b4+2];
            acc[16].x += A0*tt.x; acc[16].y += A0*tt.y;
            // r ≡ 1: B = d02 - i d13
            tt = ct_s[b4+3];
            acc[1].x  += d02*tt.x + d13*tt.y; acc[1].y  += d02*tt.y - d13*tt.x;
            acc[5].x  += d02*tt.z + d13*tt.w; acc[5].y  += d02*tt.w - d13*tt.z;
            tt = ct_s[b4+4];
            acc[9].x  += d02*tt.x + d13*tt.y; acc[9].y  += d02*tt.y - d13*tt.x;
            acc[13].x += d02*tt.z + d13*tt.w; acc[13].y += d02*tt.w - d13*tt.z;
            tt = ct_s[b4+5];
            acc[17].x += d02*tt.x + d13*tt.y; acc[17].y += d02*tt.y - d13*tt.x;
            // r ≡ 2 (real A2): r = 2,6 | 10,14 | 18
            tt = ct_s[b4+6];
            acc[2].x  += A2*tt.x; acc[2].y  += A2*tt.y; acc[6].x  += A2*tt.z; acc[6].y  += A2*tt.w;
            tt = ct_s[b4+7];
            acc[10].x += A2*tt.x; acc[10].y += A2*tt.y; acc[14].x += A2*tt.z; acc[14].y += A2*tt.w;
            tt = ct_s[b4+8];
            acc[18].x += A2*tt.x; acc[18].y += A2*tt.y;
            // r ≡ 3: B = d02 + i d13
            tt = ct_s[b4+9];
            acc[3].x  += d02*tt.x - d13*tt.y; acc[3].y  += d02*tt.y + d13*tt.x;
            acc[7].x  += d02*tt.z - d13*tt.w; acc[7].y  += d02*tt.w + d13*tt.z;
            tt = ct_s[b4+10];
            acc[11].x += d02*tt.x - d13*tt.y; acc[11].y += d02*tt.y + d13*tt.x;
            acc[15].x += d02*tt.z - d13*tt.w; acc[15].y += d02*tt.w + d13*tt.z;
            tt = ct_s[b4+11];
            acc[19].x += d02*tt.x - d13*tt.y; acc[19].y += d02*tt.y + d13*tt.x;
        }

        if (valid) {
            #pragma unroll
            for (int r = 0; r < 20; r++)
                g_Z[(r*32 + n1)*NFRF + m] = acc[r];
        }
    }
}

// complex MAC: a += z * (tx + i ty)
#define CMAC(a, z, tx, ty) do { \
    (a).x += (z).x*(tx) - (z).y*(ty); \
    (a).y += (z).x*(ty) + (z).y*(tx); } while (0)

// ---------------- fwd stage 2 (radix-4 over n1 = j + 8k):
// S[r+20q] = sum_{j<8} tw(q,j) * B_q(j),  B per q mod 4 from complex butterflies
__global__ void __launch_bounds__(128) k_stage2() {
    __shared__ float2 Zs[32][128];
    __shared__ float4 T4s[72];             // [j<8][9 float4 = 18 slots]
    int m0 = blockIdx.x * 128;
    int r  = blockIdx.y;
    int lid = threadIdx.x;

    int m = m0 + lid;
    #pragma unroll
    for (int i = 0; i < 32; i++)
        Zs[i][lid] = (m < NFRF) ? g_Z[(r*32 + i)*NFRF + m] : make_float2(0.f, 0.f);
    if (lid < 72) T4s[lid] = g_T4[lid];
    __syncthreads();

    float2 acc[17];
    #pragma unroll
    for (int q = 0; q < 17; q++) acc[q] = make_float2(0.f, 0.f);

    #pragma unroll
    for (int j = 0; j < 8; j++) {
        float2 za = Zs[j     ][lid];
        float2 zb = Zs[j + 8 ][lid];
        float2 zc = Zs[j + 16][lid];
        float2 zd = Zs[j + 24][lid];
        float2 s02 = make_float2(za.x + zc.x, za.y + zc.y);
        float2 d02 = make_float2(za.x - zc.x, za.y - zc.y);
        float2 s13 = make_float2(zb.x + zd.x, zb.y + zd.y);
        float2 d13 = make_float2(zb.x - zd.x, zb.y - zd.y);
        float2 A0 = make_float2(s02.x + s13.x, s02.y + s13.y);
        float2 A2 = make_float2(s02.x - s13.x, s02.y - s13.y);
        float2 A1 = make_float2(d02.x + d13.y, d02.y - d13.x);   // d02 - i d13
        float2 A3 = make_float2(d02.x - d13.y, d02.y + d13.x);   // d02 + i d13
        int b4 = j*9;
        float4 t;
        t = T4s[b4+0];  CMAC(acc[0],  A0, t.x, t.y);  CMAC(acc[4],  A0, t.z, t.w);
        t = T4s[b4+1];  CMAC(acc[8],  A0, t.x, t.y);  CMAC(acc[12], A0, t.z, t.w);
        t = T4s[b4+2];  CMAC(acc[16], A0, t.x, t.y);
        t = T4s[b4+3];  CMAC(acc[1],  A1, t.x, t.y);  CMAC(acc[5],  A1, t.z, t.w);
        t = T4s[b4+4];  CMAC(acc[9],  A1, t.x, t.y);  CMAC(acc[13], A1, t.z, t.w);
        t = T4s[b4+5];  CMAC(acc[2],  A2, t.x, t.y);  CMAC(acc[6],  A2, t.z, t.w);
        t = T4s[b4+6];  CMAC(acc[10], A2, t.x, t.y);  CMAC(acc[14], A2, t.z, t.w);
        t = T4s[b4+7];  CMAC(acc[3],  A3, t.x, t.y);  CMAC(acc[7],  A3, t.z, t.w);
        t = T4s[b4+8];  CMAC(acc[11], A3, t.x, t.y);  CMAC(acc[15], A3, t.z, t.w);
    }

    if (m < NFRF) {
        #pragma unroll
        for (int q = 0; q < 17; q++) {
            int f = r + 20*q;
            if (f < NF) g_S[f*NFRF + m] = acc[q];
        }
    }
}

// ---------------- covariance features ----------------
__global__ void k_cov(float* __restrict__ out) {
    int idx = blockIdx.x*blockDim.x + threadIdx.x;
    if (idx >= 2*FT) return;
    int t = idx % NT;
    int f = (idx / NT) % NF;
    int b = idx / FT;
    float2 S[8];
    #pragma unroll
    for (int c = 0; c < 8; c++)
        S[c] = g_S[f*NFRF + (b*8 + c)*NT + t];
    float* o = out + OFF_FEATS + (b*74)*FT + f*NT + t;
    int p = 0;
    #pragma unroll
    for (int i = 0; i < 8; i++) {
        #pragma unroll
        for (int j = i; j < 8; j++) {
            float re = S[i].x*S[j].x + S[i].y*S[j].y;   // S_i * conj(S_j)
            float im = S[i].y*S[j].x - S[i].x*S[j].y;
            o[(2*p    )*FT] = re;
            o[(2*p + 1)*FT] = im;
            p++;
        }
    }
    o[72*FT] = S[3].x;
    o[73*FT] = S[3].y;
}

// ---------------- padded refS (b=0) ----------------
__global__ void k_refpad() {
    int idx = blockIdx.x*blockDim.x + threadIdx.x;
    if (idx >= 323*309) return;
    int fp = idx / 309, tp = idx - fp*309;
    int f = fp - 1, t = tp - 4;
    float2 v = make_float2(0.f, 0.f);
    if (f >= 0 && f < NF && t >= 0 && t < NT)
        v = g_S[f*NFRF + 16*NT + t];
    g_rp[idx] = v;
}

// ---------------- deep filtering (b=0 only), freq-major output ----------------
__global__ void k_deepfilter(const float2* __restrict__ rtf) {
    int idx = blockIdx.x*blockDim.x + threadIdx.x;
    if (idx >= 7*FT) return;
    int t = idx % NT;
    int f = (idx / NT) % NF;
    int m = idx / FT;
    const float2* rbase = rtf + m*27*FT + f*NT + t;  // b=0: [m][27][F][T] float2
    float2 acc = make_float2(0.f, 0.f);
    #pragma unroll
    for (int ki = 0; ki < 3; ki++) {
        #pragma unroll
        for (int kj = 0; kj < 9; kj++) {
            float2 r = rbase[(ki*9 + kj)*FT];
            float2 p = g_rp[(f + ki)*309 + (t + kj)];
            acc.x += r.x*p.x - r.y*p.y;
            acc.y += r.x*p.y + r.y*p.x;
        }
    }
    g_estF[f*MINV + m*NT + t] = acc;   // [k][R], R = m*NT + t
}

// ---------------- inv stage A: A1[r][n1][R] = sum_q ck*E[20q+r][R]*e^{+2pi i k n1/640}
// block 256 = 2 groups of 128; group g computes n1 in [16g, 16g+16)
__global__ void __launch_bounds__(256) k_istageA() {
    __shared__ float2 Es[17][128];
    __shared__ float2 TAs[17*32];
    int m0 = blockIdx.x * 128;
    int r  = blockIdx.y;
    int tid = threadIdx.x;
    int lid = tid & 127;
    int grp = tid >> 7;
    const float4* TAs4 = (const float4*)TAs;

    for (int e = tid; e < 544; e += 256) TAs[e] = g_TA[r*544 + e];
    for (int e = tid; e < 17*128; e += 256) {
        int q = e >> 7, ml = e & 127;
        int k = 20*q + r;
        int Rm = m0 + ml;
        Es[q][ml] = (k < NF && Rm < MINV) ? g_estF[k*MINV + Rm] : make_float2(0.f, 0.f);
    }
    __syncthreads();

    float2 acc[16];
    #pragma unroll
    for (int j = 0; j < 16; j++) acc[j] = make_float2(0.f, 0.f);

    #pragma unroll
    for (int q = 0; q < 17; q++) {
        float2 a = Es[q][lid];
        #pragma unroll
        for (int j = 0; j < 8; j++) {
            float4 t = TAs4[q*16 + grp*8 + j];
            acc[2*j  ].x += a.x*t.x - a.y*t.y;
            acc[2*j  ].y += a.x*t.y + a.y*t.x;
            acc[2*j+1].x += a.x*t.z - a.y*t.w;
            acc[2*j+1].y += a.x*t.w + a.y*t.z;
        }
    }

    int R = m0 + lid;
    int n1b = grp*16;
    if (R < MINV) {
        #pragma unroll
        for (int j = 0; j < 16; j++)
            g_A1[(r*32 + n1b + j)*MINV + R] = acc[j];
    }
}

// ---------------- inv stage B: y[R][n] = win[n]/640 * Re(sum_r A1[r][n1][R]*e^{+2pi i r n2/20})
__global__ void __launch_bounds__(256) k_istageB() {
    __shared__ float2 A1s[20][8][33];    // [r][mloc][n1] (pad to 33 for conflict-free)
    __shared__ float2 TBs[400];          // transposed [n2][r]
    __shared__ float  wins[NFFT];
    int R0 = blockIdx.x * 8;
    int lid = threadIdx.x;
    const float4* TBs4 = (const float4*)TBs;

    #pragma unroll
    for (int e = lid; e < 400; e += 256) TBs[e] = g_TBt[e];
    #pragma unroll
    for (int e = lid; e < NFFT; e += 256) wins[e] = g_win[e] * (1.0f/640.0f);
    #pragma unroll
    for (int i = 0; i < 20; i++) {
        int e = i*256 + lid;
        int rn1 = e >> 3, mloc = e & 7;
        int r = rn1 >> 5, n1 = rn1 & 31;
        int R = R0 + mloc;
        A1s[r][mloc][n1] = (R < MINV) ? g_A1[rn1*MINV + R] : make_float2(0.f, 0.f);
    }
    __syncthreads();

    #pragma unroll
    for (int mloc = 0; mloc < 8; mloc++) {
        int R = R0 + mloc;
        if (R >= MINV) break;    // uniform across block
        #pragma unroll
        for (int nb = 0; nb < 3; nb++) {
            int n = nb*256 + lid;
            if (n < NFFT) {
                int n1 = n & 31, n2 = n >> 5;
                float acc = 0.0f;
                #pragma unroll
                for (int jr = 0; jr < 10; jr++) {       // r = 2jr, 2jr+1
                    float4 t = TBs4[n2*10 + jr];
                    float2 a0 = A1s[2*jr  ][mloc][n1];
                    float2 a1 = A1s[2*jr+1][mloc][n1];
                    acc += a0.x*t.x - a0.y*t.y;
                    acc += a1.x*t.z - a1.y*t.w;
                }
                g_y[R*NFFT + n] = acc * wins[n];
            }
        }
    }
}

// ---------------- overlap-add + interleave output ----------------
__global__ void k_ola(const float* __restrict__ ref, float* __restrict__ out) {
    int s = blockIdx.x*blockDim.x + threadIdx.x;
    if (s >= TLEN) return;
    int sp = s + HOP;                 // position in uncropped signal
    int t1 = sp / HOP;                // in [1, 300]
    int n1 = sp - t1*HOP;             // [0, 320)
    int t0 = t1 - 1;
    int nn0 = n1 + HOP;               // [320, 640)
    float iw = g_invw[sp];
    float* o = out + s*8;
    #pragma unroll
    for (int m = 0; m < 7; m++) {
        float v = (g_y[(m*NT + t0)*NFFT + nn0] + g_y[(m*NT + t1)*NFFT + n1]) * iw;
        o[m < 3 ? m : m + 1] = v;
    }
    o[3] = ref[s];
}

// ---------------- launch (serial; stream forking proved useless here) ---------
extern "C" void kernel_launch(void* const* d_in, const int* in_sizes, int n_in,
                              void* d_out, int out_size) {
    const float*  x   = (const float*)d_in[0];
    const float2* rtf = (const float2*)d_in[1];  // [B][7][3][9][F][T][2]; b=0 slice
    const float*  ref = (const float*)d_in[2];   // [2][1][T]; b=0 slice
    float* out = (float*)d_out;

    cudaFuncSetAttribute(k_fs1, cudaFuncAttributeMaxDynamicSharedMemorySize, FS1_SMEM);

    k_tab<<<(TAB_END + 255)/256, 256>>>();
    {
        dim3 g((NT + 15)/16, NCHF);          // 19 t-tiles x 17 channels
        k_fs1<<<g, 256, FS1_SMEM>>>(x, ref);
    }
    {
        dim3 g((NFRF + 127)/128, 20);
        k_stage2<<<g, 128>>>();
    }
    k_cov<<<(2*FT + 255)/256, 256>>>(out);
    k_refpad<<<(323*309 + 255)/256, 256>>>();
    k_deepfilter<<<(7*FT + 255)/256, 256>>>(rtf);
    {
        dim3 g((MINV + 127)/128, 20);
        k_istageA<<<g, 256>>>();
    }
    {
        dim3 g((MINV + 7)/8);
        k_istageB<<<g, 256>>>();
    }
    k_ola<<<(TLEN + 255)/256, 256>>>(ref, out);
}